// round 14
// baseline (speedup 1.0000x reference)
#include <cuda_runtime.h>
#include <cuda_fp16.h>
#include <cstdint>

// ---------------- problem constants ----------------
#define BATCH  4
#define QLEN   1024
#define KLEN   2048
#define DMODEL 2048
#define FLEN   1025

#define INV_SQRT_FLEN 0.031234752f    // 1/sqrt(1025)
#define SCALE_OUT     0.022097087f    // 1/sqrt(2048)

// GEMM tiling: 64-thread CTAs, 2 warps (1x2), 64x64 warp tiles, BM=64
// Band support per CTA: [m0, m0+1088) = 17 tiles of 64 — uniform across warps.
#define BM 64
#define BN 128
#define BK 64
#define KITERS 17                     // 1088 = 17*64
#define NTHREADS 64
#define A_TILE_BYTES (64 * 128)       // 64 m-rows x 64 fp16 (128 B)
#define B_TILE_BYTES (64 * 256)       // 64 k-rows x 128 fp16 (256 B)
#define STAGE_BYTES  (A_TILE_BYTES + B_TILE_BYTES)   // 24 KB
#define NSTAGES 2
#define SMEM_BYTES   (NSTAGES * STAGE_BYTES)         // 48 KB

// ---------------- device scratch (no allocations allowed) ----------------
__device__ __half g_ft[(size_t)QLEN * KLEN];                 // [l][k], banded
__device__ __half g_xk[(size_t)BATCH * KLEN * DMODEL];       // [b][k][d] fp16

// ---------------- PTX helpers ----------------
__device__ __forceinline__ uint32_t smem_to_u32(const void* smem_ptr) {
    uint32_t addr;
    asm("{ .reg .u64 tmp; cvta.to.shared.u64 tmp, %1; cvt.u32.u64 %0, tmp; }"
        : "=r"(addr) : "l"(smem_ptr));
    return addr;
}

#define CP_ASYNC16(dst_u32, src_ptr) \
    asm volatile("cp.async.cg.shared.global [%0], [%1], 16;" \
                 :: "r"(dst_u32), "l"(src_ptr))

#define CP_COMMIT() asm volatile("cp.async.commit_group;" ::: "memory")
#define CP_WAIT0()  asm volatile("cp.async.wait_group 0;" ::: "memory")

#define LDSM_X4(r, addr) \
    asm volatile("ldmatrix.sync.aligned.m8n8.x4.shared.b16 {%0,%1,%2,%3}, [%4];" \
        : "=r"((r)[0]), "=r"((r)[1]), "=r"((r)[2]), "=r"((r)[3]) : "r"(addr))

#define LDSM_X4_T(r, addr) \
    asm volatile("ldmatrix.sync.aligned.m8n8.x4.trans.shared.b16 {%0,%1,%2,%3}, [%4];" \
        : "=r"((r)[0]), "=r"((r)[1]), "=r"((r)[2]), "=r"((r)[3]) : "r"(addr))

#define MMA16816(c, a, b0, b1) \
    asm volatile("mma.sync.aligned.m16n8k16.row.col.f32.f16.f16.f32 " \
        "{%0,%1,%2,%3}, {%4,%5,%6,%7}, {%8,%9}, {%0,%1,%2,%3};" \
        : "+f"((c)[0]), "+f"((c)[1]), "+f"((c)[2]), "+f"((c)[3]) \
        : "r"((a)[0]), "r"((a)[1]), "r"((a)[2]), "r"((a)[3]), "r"(b0), "r"(b1))

// ---------------- prep kernel (fused, interleaved) ----------------
// 2 of every 3 blocks: g_xk[b][k][d] = fp16(x (+p))   (streaming, DRAM-bound)
// 1 of every 3 blocks: banded FT in fp16 (MUFU-bound) — interleaved to overlap.
//   FT[l,k] = cos(2*pi*l*(k-l)/1025)/sqrt(1025) for l <= k <= l+1024, else 0.
#define XT_BLOCKS 16384   // 16.7M elements / (256 thr * 4 elem)
#define FT_BLOCKS 8192    // 2M elements / 256

__global__ void __launch_bounds__(256)
prep_kernel(const float* __restrict__ x, const float* __restrict__ p,
            const int* __restrict__ add_pos) {
    int bi = blockIdx.x;
    if (bi % 3 != 2) {
        int xi = (bi / 3) * 2 + (bi % 3);        // 0..XT_BLOCKS-1
        size_t e0 = ((size_t)xi * 256 + threadIdx.x) * 4;
        float4 xs = *reinterpret_cast<const float4*>(x + e0);
        if (*add_pos) {
            float4 ps = *reinterpret_cast<const float4*>(p + e0);
            xs.x += ps.x; xs.y += ps.y; xs.z += ps.z; xs.w += ps.w;
        }
        __half2 h0 = __floats2half2_rn(xs.x, xs.y);
        __half2 h1 = __floats2half2_rn(xs.z, xs.w);
        *reinterpret_cast<__half2*>(g_xk + e0)     = h0;
        *reinterpret_cast<__half2*>(g_xk + e0 + 2) = h1;
    } else {
        int fi = bi / 3;                          // 0..FT_BLOCKS-1
        int idx = fi * 256 + threadIdx.x;
        int l = idx >> 11;
        int k = idx & (KLEN - 1);
        int j = k - l;
        float v = 0.0f;
        if (j >= 0 && j < FLEN) {
            int r = (l * j) % FLEN;              // fits int32
            v = cospif(2.0f * (float)r / (float)FLEN) * INV_SQRT_FLEN;
        }
        g_ft[idx] = __float2half_rn(v);
    }
}

// ---------------- banded GEMM via mma.sync fp16 ------------------------------
// Stage layout: A @0  (64 m-rows x 128 B, chunk swizzle c ^ (row&7)),
//               B @8K (64 k-rows x 256 B, chunk swizzle c ^ (row&7)).
// ldsm addresses precomputed; kstep stepping: A addr ^= (ks<<5),
// B addr += ks*4096 (row&7 invariant under +16 rows).
// Pipeline: CP_WAIT0 -> __syncthreads -> fill kt+1 (async) -> compute kt.
// Triangular edge-tile skipping (CTA-uniform, exact):
//   kt==0:        MMA (mi,ks) all-zero unless mi <= ks  (FT needs l <= k)
//   kt==KITERS-1: MMA (mi,ks) all-zero unless ks <= mi  (FT needs k <= l+1024)
// Skipped A sub-blocks are exact zeros -> bit-identical result, 4.4% less work.
__global__ void __launch_bounds__(NTHREADS, 4)
gemm_kernel(float* __restrict__ out) {
    extern __shared__ char smem[];
    const uint32_t sbase = smem_to_u32(smem);
    const int tid  = threadIdx.x;
    const int lane = tid & 31;
    const int wn   = tid >> 5;   // 2 warps in N (64 cols each)

    const int d0 = blockIdx.x * BN;
    const int m0 = blockIdx.y * BM;
    const int b  = blockIdx.z;

    const __half* gA = g_ft + (size_t)m0 * KLEN;                       // [m][k]
    const __half* gB = g_xk + (size_t)b * KLEN * DMODEL + d0;          // [k][d]

    // ---- precomputed ldsm base offsets (relative to stage base) ----
    uint32_t a_base[4];
    #pragma unroll
    for (int mi = 0; mi < 4; mi++) {
        int row_s = mi * 16 + (lane & 15);
        int chunk = lane >> 4;                       // ks adds 2*ks (no carry)
        a_base[mi] = row_s * 128 + ((chunk ^ (row_s & 7)) << 4);
    }
    uint32_t b_base[4];
    #pragma unroll
    for (int pr = 0; pr < 4; pr++) {                 // covers ntiles 2pr, 2pr+1
        int g8    = lane >> 3;
        int ntile = pr * 2 + (g8 >> 1);
        int khalf = g8 & 1;
        int row_s = khalf * 8 + (lane & 7);          // ks adds 16 rows (+4096 B)
        int chunk = wn * 8 + ntile;                  // 16B chunks within 256B row
        b_base[pr] = A_TILE_BYTES + row_s * 256 + ((chunk ^ (row_s & 7)) << 4);
    }

    // ---- stage loader: 24 x 16B cp.async per thread (A: 8, B: 16) ----
    auto load_stage = [&](uint32_t so, int k0) {
        #pragma unroll
        for (int i = 0; i < 8; i++) {          // A: 512 chunks of 16 B
            int idx = i * 64 + tid;
            int r = idx >> 3, c = idx & 7;
            int csw = c ^ (r & 7);
            CP_ASYNC16(so + r * 128 + (csw << 4),
                       gA + (size_t)r * KLEN + k0 + c * 8);
        }
        #pragma unroll
        for (int i = 0; i < 16; i++) {         // B: 1024 chunks of 16 B
            int idx = i * 64 + tid;
            int r = idx >> 4, c = idx & 15;
            int csw = c ^ (r & 7);
            CP_ASYNC16(so + A_TILE_BYTES + r * 256 + (csw << 4),
                       gB + (size_t)(k0 + r) * DMODEL + c * 8);
        }
        CP_COMMIT();
    };

    float acc[4][8][4] = {};   // [mi][ni][4] = 128 floats

    load_stage(sbase, m0);                 // tile 0; band starts at k = m0

    for (int kt = 0; kt < KITERS; kt++) {
        CP_WAIT0();                        // this thread's copies of tile kt done
        __syncthreads();                   // all copies visible; old stage free
        if (kt + 1 < KITERS)               // fill tile kt+1 (overlaps compute)
            load_stage(sbase + ((kt + 1) & 1) * STAGE_BYTES, m0 + (kt + 1) * BK);

        const uint32_t soff = sbase + (kt & 1) * STAGE_BYTES;
        const bool lo = (kt == 0);             // require mi <= ks
        const bool hi = (kt == KITERS - 1);    // require ks <= mi

        #pragma unroll
        for (int ks = 0; ks < 4; ks++) {
            uint32_t af[4][4];
            uint32_t bfr[4][4];
            #pragma unroll
            for (int mi = 0; mi < 4; mi++)
                if ((!lo || mi <= ks) && (!hi || ks <= mi))
                    LDSM_X4(af[mi], (soff + a_base[mi]) ^ (ks << 5));
            LDSM_X4_T(bfr[0], soff + b_base[0] + ks * 4096);
            LDSM_X4_T(bfr[1], soff + b_base[1] + ks * 4096);
            #pragma unroll
            for (int mi = 0; mi < 4; mi++)
                if ((!lo || mi <= ks) && (!hi || ks <= mi)) {
                    #pragma unroll
                    for (int ni = 0; ni < 4; ni++)
                        MMA16816(acc[mi][ni], af[mi],
                                 bfr[ni >> 1][(ni & 1) * 2],
                                 bfr[ni >> 1][(ni & 1) * 2 + 1]);
                }
            LDSM_X4_T(bfr[2], soff + b_base[2] + ks * 4096);
            LDSM_X4_T(bfr[3], soff + b_base[3] + ks * 4096);
            #pragma unroll
            for (int mi = 0; mi < 4; mi++)
                if ((!lo || mi <= ks) && (!hi || ks <= mi)) {
                    #pragma unroll
                    for (int ni = 4; ni < 8; ni++)
                        MMA16816(acc[mi][ni], af[mi],
                                 bfr[ni >> 1][(ni & 1) * 2],
                                 bfr[ni >> 1][(ni & 1) * 2 + 1]);
                }
        }
    }

    // ---- epilogue: scale + float2 stores ----
    #pragma unroll
    for (int mi = 0; mi < 4; mi++) {
        #pragma unroll
        for (int ni = 0; ni < 8; ni++) {
            int row = m0 + mi * 16 + (lane >> 2);
            int col = d0 + wn * 64 + ni * 8 + (lane & 3) * 2;
            float* o = out + ((size_t)b * QLEN + row) * DMODEL + col;
            float2 v0 = {acc[mi][ni][0] * SCALE_OUT, acc[mi][ni][1] * SCALE_OUT};
            float2 v1 = {acc[mi][ni][2] * SCALE_OUT, acc[mi][ni][3] * SCALE_OUT};
            *reinterpret_cast<float2*>(o) = v0;
            *reinterpret_cast<float2*>(o + 8 * DMODEL) = v1;
        }
    }
}

// ---------------- launch ----------------
extern "C" void kernel_launch(void* const* d_in, const int* in_sizes, int n_in,
                              void* d_out, int out_size) {
    const float* x = (const float*)d_in[0];
    const float* p = (const float*)d_in[1];
    // d_in[2] = qlen (fixed 1024 by problem shape), d_in[3] = add_position flag
    const int* add_pos = (const int*)d_in[3];
    float* out = (float*)d_out;

    cudaFuncSetAttribute(gemm_kernel,
                         cudaFuncAttributeMaxDynamicSharedMemorySize, SMEM_BYTES);

    prep_kernel<<<XT_BLOCKS + FT_BLOCKS, 256>>>(x, p, add_pos);
    gemm_kernel<<<dim3(DMODEL / BN, QLEN / BM, BATCH), NTHREADS, SMEM_BYTES>>>(out);
}

// round 15
// speedup vs baseline: 1.0271x; 1.0271x over previous
#include <cuda_runtime.h>
#include <cuda_fp16.h>
#include <cstdint>

// ---------------- problem constants ----------------
#define BATCH  4
#define QLEN   1024
#define KLEN   2048
#define DMODEL 2048
#define FLEN   1025

#define INV_SQRT_FLEN 0.031234752f    // 1/sqrt(1025)
#define SCALE_OUT     0.022097087f    // 1/sqrt(2048)

// GEMM tiling: 64-thread CTAs, 2 warps (1x2), 64x64 warp tiles, BM=64
// Band support per CTA: [m0, m0+1088) = 17 tiles of 64 — uniform across warps.
#define BM 64
#define BN 128
#define BK 64
#define KITERS 17                     // 1088 = 17*64
#define NTHREADS 64
#define A_TILE_BYTES (64 * 128)       // 64 m-rows x 64 fp16 (128 B)
#define B_TILE_BYTES (64 * 256)       // 64 k-rows x 128 fp16 (256 B)
#define STAGE_BYTES  (A_TILE_BYTES + B_TILE_BYTES)   // 24 KB
#define NSTAGES 2
#define SMEM_BYTES   (NSTAGES * STAGE_BYTES)         // 48 KB

// ---------------- device scratch (no allocations allowed) ----------------
__device__ __half g_ft[(size_t)QLEN * KLEN];                 // [l][k], banded
__device__ __half g_xk[(size_t)BATCH * KLEN * DMODEL];       // [b][k][d] fp16

// ---------------- PTX helpers ----------------
__device__ __forceinline__ uint32_t smem_to_u32(const void* smem_ptr) {
    uint32_t addr;
    asm("{ .reg .u64 tmp; cvta.to.shared.u64 tmp, %1; cvt.u32.u64 %0, tmp; }"
        : "=r"(addr) : "l"(smem_ptr));
    return addr;
}

#define CP_ASYNC16(dst_u32, src_ptr) \
    asm volatile("cp.async.cg.shared.global [%0], [%1], 16;" \
                 :: "r"(dst_u32), "l"(src_ptr))

#define CP_COMMIT() asm volatile("cp.async.commit_group;" ::: "memory")
#define CP_WAIT0()  asm volatile("cp.async.wait_group 0;" ::: "memory")

#define LDSM_X4(r, addr) \
    asm volatile("ldmatrix.sync.aligned.m8n8.x4.shared.b16 {%0,%1,%2,%3}, [%4];" \
        : "=r"((r)[0]), "=r"((r)[1]), "=r"((r)[2]), "=r"((r)[3]) : "r"(addr))

#define LDSM_X4_T(r, addr) \
    asm volatile("ldmatrix.sync.aligned.m8n8.x4.trans.shared.b16 {%0,%1,%2,%3}, [%4];" \
        : "=r"((r)[0]), "=r"((r)[1]), "=r"((r)[2]), "=r"((r)[3]) : "r"(addr))

#define MMA16816(c, a, b0, b1) \
    asm volatile("mma.sync.aligned.m16n8k16.row.col.f32.f16.f16.f32 " \
        "{%0,%1,%2,%3}, {%4,%5,%6,%7}, {%8,%9}, {%0,%1,%2,%3};" \
        : "+f"((c)[0]), "+f"((c)[1]), "+f"((c)[2]), "+f"((c)[3]) \
        : "r"((a)[0]), "r"((a)[1]), "r"((a)[2]), "r"((a)[3]), "r"(b0), "r"(b1))

// ---------------- prep kernels ----------------
// xt: g_xk[b][k][d] = fp16(x (+p)); layout is b-major, so element ranges map
// directly to batch ranges. ft: banded FT in fp16:
//   FT[l,k] = cos(2*pi*l*(k-l)/1025)/sqrt(1025) for l <= k <= l+1024, else 0.

__device__ __forceinline__ void xt_block(int xi, const float* __restrict__ x,
                                         const float* __restrict__ p, int ap) {
    size_t e0 = ((size_t)xi * 256 + threadIdx.x) * 4;
    float4 xs = *reinterpret_cast<const float4*>(x + e0);
    if (ap) {
        float4 ps = *reinterpret_cast<const float4*>(p + e0);
        xs.x += ps.x; xs.y += ps.y; xs.z += ps.z; xs.w += ps.w;
    }
    __half2 h0 = __floats2half2_rn(xs.x, xs.y);
    __half2 h1 = __floats2half2_rn(xs.z, xs.w);
    *reinterpret_cast<__half2*>(g_xk + e0)     = h0;
    *reinterpret_cast<__half2*>(g_xk + e0 + 2) = h1;
}

// prep01: interleaved ft (8192 blocks) + xt for b=0,1 (8192 blocks)
__global__ void __launch_bounds__(256)
prep01_kernel(const float* __restrict__ x, const float* __restrict__ p,
              const int* __restrict__ add_pos) {
    int bi = blockIdx.x;
    if (bi & 1) {
        xt_block(bi >> 1, x, p, *add_pos);       // xi in [0, 8192)
    } else {
        int idx = (bi >> 1) * 256 + threadIdx.x; // ft index
        int l = idx >> 11;
        int k = idx & (KLEN - 1);
        int j = k - l;
        float v = 0.0f;
        if (j >= 0 && j < FLEN) {
            int r = (l * j) % FLEN;              // fits int32
            v = cospif(2.0f * (float)r / (float)FLEN) * INV_SQRT_FLEN;
        }
        g_ft[idx] = __float2half_rn(v);
    }
}

// prep23: xt for b=2,3 (8192 blocks)
__global__ void __launch_bounds__(256)
prep23_kernel(const float* __restrict__ x, const float* __restrict__ p,
              const int* __restrict__ add_pos) {
    xt_block(8192 + blockIdx.x, x, p, *add_pos);  // xi in [8192, 16384)
}

// ---------------- banded GEMM via mma.sync fp16 ------------------------------
// Stage layout: A @0  (64 m-rows x 128 B, chunk swizzle c ^ (row&7)),
//               B @8K (64 k-rows x 256 B, chunk swizzle c ^ (row&7)).
// ldsm addresses precomputed; kstep stepping: A addr ^= (ks<<5),
// B addr += ks*4096 (row&7 invariant under +16 rows).
// Pipeline: CP_WAIT0 -> __syncthreads -> fill kt+1 (async) -> compute kt.
// Triangular edge-tile skipping (CTA-uniform, exact):
//   kt==0:        MMA (mi,ks) all-zero unless mi <= ks
//   kt==KITERS-1: MMA (mi,ks) all-zero unless ks <= mi
__global__ void __launch_bounds__(NTHREADS, 4)
gemm_kernel(float* __restrict__ out, int boff) {
    extern __shared__ char smem[];
    const uint32_t sbase = smem_to_u32(smem);
    const int tid  = threadIdx.x;
    const int lane = tid & 31;
    const int wn   = tid >> 5;   // 2 warps in N (64 cols each)

    const int d0 = blockIdx.x * BN;
    const int m0 = blockIdx.y * BM;
    const int b  = boff + blockIdx.z;

    const __half* gA = g_ft + (size_t)m0 * KLEN;                       // [m][k]
    const __half* gB = g_xk + (size_t)b * KLEN * DMODEL + d0;          // [k][d]

    // ---- precomputed ldsm base offsets (relative to stage base) ----
    uint32_t a_base[4];
    #pragma unroll
    for (int mi = 0; mi < 4; mi++) {
        int row_s = mi * 16 + (lane & 15);
        int chunk = lane >> 4;                       // ks adds 2*ks (no carry)
        a_base[mi] = row_s * 128 + ((chunk ^ (row_s & 7)) << 4);
    }
    uint32_t b_base[4];
    #pragma unroll
    for (int pr = 0; pr < 4; pr++) {                 // covers ntiles 2pr, 2pr+1
        int g8    = lane >> 3;
        int ntile = pr * 2 + (g8 >> 1);
        int khalf = g8 & 1;
        int row_s = khalf * 8 + (lane & 7);          // ks adds 16 rows (+4096 B)
        int chunk = wn * 8 + ntile;                  // 16B chunks within 256B row
        b_base[pr] = A_TILE_BYTES + row_s * 256 + ((chunk ^ (row_s & 7)) << 4);
    }

    // ---- stage loader: 24 x 16B cp.async per thread (A: 8, B: 16) ----
    auto load_stage = [&](uint32_t so, int k0) {
        #pragma unroll
        for (int i = 0; i < 8; i++) {          // A: 512 chunks of 16 B
            int idx = i * 64 + tid;
            int r = idx >> 3, c = idx & 7;
            int csw = c ^ (r & 7);
            CP_ASYNC16(so + r * 128 + (csw << 4),
                       gA + (size_t)r * KLEN + k0 + c * 8);
        }
        #pragma unroll
        for (int i = 0; i < 16; i++) {         // B: 1024 chunks of 16 B
            int idx = i * 64 + tid;
            int r = idx >> 4, c = idx & 15;
            int csw = c ^ (r & 7);
            CP_ASYNC16(so + A_TILE_BYTES + r * 256 + (csw << 4),
                       gB + (size_t)(k0 + r) * DMODEL + c * 8);
        }
        CP_COMMIT();
    };

    float acc[4][8][4] = {};   // [mi][ni][4] = 128 floats

    load_stage(sbase, m0);                 // tile 0; band starts at k = m0

    for (int kt = 0; kt < KITERS; kt++) {
        CP_WAIT0();                        // this thread's copies of tile kt done
        __syncthreads();                   // all copies visible; old stage free
        if (kt + 1 < KITERS)               // fill tile kt+1 (overlaps compute)
            load_stage(sbase + ((kt + 1) & 1) * STAGE_BYTES, m0 + (kt + 1) * BK);

        const uint32_t soff = sbase + (kt & 1) * STAGE_BYTES;
        const bool lo = (kt == 0);             // require mi <= ks
        const bool hi = (kt == KITERS - 1);    // require ks <= mi

        #pragma unroll
        for (int ks = 0; ks < 4; ks++) {
            uint32_t af[4][4];
            uint32_t bfr[4][4];
            #pragma unroll
            for (int mi = 0; mi < 4; mi++)
                if ((!lo || mi <= ks) && (!hi || ks <= mi))
                    LDSM_X4(af[mi], (soff + a_base[mi]) ^ (ks << 5));
            LDSM_X4_T(bfr[0], soff + b_base[0] + ks * 4096);
            LDSM_X4_T(bfr[1], soff + b_base[1] + ks * 4096);
            #pragma unroll
            for (int mi = 0; mi < 4; mi++)
                if ((!lo || mi <= ks) && (!hi || ks <= mi)) {
                    #pragma unroll
                    for (int ni = 0; ni < 4; ni++)
                        MMA16816(acc[mi][ni], af[mi],
                                 bfr[ni >> 1][(ni & 1) * 2],
                                 bfr[ni >> 1][(ni & 1) * 2 + 1]);
                }
            LDSM_X4_T(bfr[2], soff + b_base[2] + ks * 4096);
            LDSM_X4_T(bfr[3], soff + b_base[3] + ks * 4096);
            #pragma unroll
            for (int mi = 0; mi < 4; mi++)
                if ((!lo || mi <= ks) && (!hi || ks <= mi)) {
                    #pragma unroll
                    for (int ni = 4; ni < 8; ni++)
                        MMA16816(acc[mi][ni], af[mi],
                                 bfr[ni >> 1][(ni & 1) * 2],
                                 bfr[ni >> 1][(ni & 1) * 2 + 1]);
                }
        }
    }

    // ---- epilogue: scale + float2 stores ----
    #pragma unroll
    for (int mi = 0; mi < 4; mi++) {
        #pragma unroll
        for (int ni = 0; ni < 8; ni++) {
            int row = m0 + mi * 16 + (lane >> 2);
            int col = d0 + wn * 64 + ni * 8 + (lane & 3) * 2;
            float* o = out + ((size_t)b * QLEN + row) * DMODEL + col;
            float2 v0 = {acc[mi][ni][0] * SCALE_OUT, acc[mi][ni][1] * SCALE_OUT};
            float2 v1 = {acc[mi][ni][2] * SCALE_OUT, acc[mi][ni][3] * SCALE_OUT};
            *reinterpret_cast<float2*>(o) = v0;
            *reinterpret_cast<float2*>(o + 8 * DMODEL) = v1;
        }
    }
}

// ---------------- launch: forked schedule -------------------------------
// stream0: prep01 (ft + xt b0,b1) -> [e0] -> gemm(b0,b1)
// s1:      wait e0 -> prep23 (xt b2,b3) -> gemm(b2,b3) -> [e1]
// stream0: wait e1
// prep23 overlaps gemm01 (DRAM-heavy || DRAM-light); gemm23 overlaps
// gemm01's tail wave, packing the SM slots both grids underfill alone.
extern "C" void kernel_launch(void* const* d_in, const int* in_sizes, int n_in,
                              void* d_out, int out_size) {
    const float* x = (const float*)d_in[0];
    const float* p = (const float*)d_in[1];
    // d_in[2] = qlen (fixed 1024 by problem shape), d_in[3] = add_position flag
    const int* add_pos = (const int*)d_in[3];
    float* out = (float*)d_out;

    // One-time infra (first call = correctness run, outside graph capture).
    // Work enqueued per call is identical -> deterministic & capturable.
    static cudaStream_t s1 = nullptr;
    static cudaEvent_t e0 = nullptr, e1 = nullptr;
    if (s1 == nullptr) {
        cudaStreamCreateWithFlags(&s1, cudaStreamNonBlocking);
        cudaEventCreateWithFlags(&e0, cudaEventDisableTiming);
        cudaEventCreateWithFlags(&e1, cudaEventDisableTiming);
        cudaFuncSetAttribute(gemm_kernel,
                             cudaFuncAttributeMaxDynamicSharedMemorySize,
                             SMEM_BYTES);
    }

    prep01_kernel<<<16384, 256>>>(x, p, add_pos);
    cudaEventRecord(e0, 0);
    gemm_kernel<<<dim3(DMODEL / BN, QLEN / BM, 2), NTHREADS, SMEM_BYTES>>>(out, 0);

    cudaStreamWaitEvent(s1, e0, 0);
    prep23_kernel<<<8192, 256, 0, s1>>>(x, p, add_pos);
    gemm_kernel<<<dim3(DMODEL / BN, QLEN / BM, 2), NTHREADS, SMEM_BYTES, s1>>>(out, 2);
    cudaEventRecord(e1, s1);

    cudaStreamWaitEvent(0, e1, 0);
}